// round 3
// baseline (speedup 1.0000x reference)
#include <cuda_runtime.h>
#include <math.h>

#define NTOK 8192
#define SEQL 1024
#define EMBD 512
#define NUMC 10000

// ---------------- scratch (device globals; no allocation allowed) ----------------
__device__ float g_x  [NTOK*EMBD];
__device__ float g_qsh[NTOK*EMBD];
__device__ float g_qp [NTOK*EMBD];
__device__ float g_kp [NTOK*EMBD];
__device__ float g_vp [NTOK*EMBD];
__device__ float g_t0 [NTOK*EMBD];
__device__ float g_t1 [NTOK*EMBD];
__device__ float g_h  [NTOK*EMBD];
__device__ float g_t2 [NTOK*EMBD];
__device__ float g_m  [SEQL];

// ---------------- prep: mask m[t] + L1(alphas) ----------------
__global__ void prep_kernel(const float* __restrict__ alphas,
                            const float* __restrict__ gumbel,
                            float* __restrict__ out, int write_l1) {
    int t = threadIdx.x; // 1024 threads
    float a0 = alphas[2*t], a1 = alphas[2*t+1];
    float l0 = a0 + gumbel[2*t], l1 = a1 + gumbel[2*t+1];
    // argmax(softmax) == argmax(logits); jnp.argmax picks first on tie -> >=
    g_m[t] = (l0 >= l1) ? 1.0f : 0.0f;

    float v = fabsf(a0) + fabsf(a1);
    __shared__ float red[32];
    #pragma unroll
    for (int o = 16; o; o >>= 1) v += __shfl_down_sync(0xffffffffu, v, o);
    if ((t & 31) == 0) red[t >> 5] = v;
    __syncthreads();
    if (t < 32) {
        float w = red[t];
        #pragma unroll
        for (int o = 16; o; o >>= 1) w += __shfl_down_sync(0xffffffffu, w, o);
        if (t == 0 && write_l1) out[NTOK] = w;
    }
}

// ---------------- gather: x = inter[q+C*r]+pos ; qsh = ex[qry] ----------------
__global__ __launch_bounds__(128) void gather_kernel(
        const int* __restrict__ q, const int* __restrict__ r,
        const int* __restrict__ qry,
        const float* __restrict__ inter, const float* __restrict__ ex,
        const float* __restrict__ pos) {
    int n = blockIdx.x, t = threadIdx.x;            // t in [0,128): float4 lanes
    int li = n & (SEQL - 1);
    long ii = (long)(q[n] + NUMC * r[n]) * 128;
    long ei = (long)qry[n] * 128;
    float4 iv = ((const float4*)inter)[ii + t];
    float4 pv = ((const float4*)pos)[li * 128 + t];
    float4 xv;
    xv.x = iv.x + pv.x; xv.y = iv.y + pv.y; xv.z = iv.z + pv.z; xv.w = iv.w + pv.w;
    ((float4*)g_x)[n * 128 + t] = xv;
    ((float4*)g_qsh)[n * 128 + t] = ((const float4*)ex)[ei + t];
}

// ---------------- shared SGEMM core: 128x128 tile, BK=8, double-buffered -------
// C[row0.., col0..] = A[N,512] @ W[wrow0..,512]^T + bias (opt relu)
__device__ __forceinline__ void sgemm_core(
        const float* __restrict__ A, const float* __restrict__ W,
        const float* __restrict__ bias, float* __restrict__ C,
        int row0, int col0, int wrow0, int bias0, int relu) {
    __shared__ float As[2][8][128];
    __shared__ float Bs[2][8][128];
    int tid = threadIdx.x;
    int lr = tid >> 1;             // 0..127
    int lc = (tid & 1) * 4;        // 0 or 4
    const float* Aptr = A + (row0 + lr) * EMBD + lc;
    const float* Wptr = W + (wrow0 + lr) * EMBD + lc;
    int ty = tid >> 4, tx = tid & 15;
    float acc[8][8];
    #pragma unroll
    for (int i = 0; i < 8; i++)
        #pragma unroll
        for (int j = 0; j < 8; j++) acc[i][j] = 0.f;

    // prologue: tile 0
    {
        float4 av = *(const float4*)(Aptr);
        float4 wv = *(const float4*)(Wptr);
        As[0][lc+0][lr] = av.x; As[0][lc+1][lr] = av.y;
        As[0][lc+2][lr] = av.z; As[0][lc+3][lr] = av.w;
        Bs[0][lc+0][lr] = wv.x; Bs[0][lc+1][lr] = wv.y;
        Bs[0][lc+2][lr] = wv.z; Bs[0][lc+3][lr] = wv.w;
    }
    __syncthreads();

    const int NT = EMBD / 8;       // 64 tiles
    // mainloop: tiles 0..NT-2, each prefetching t+1 (branch-free body)
    for (int t = 0; t < NT - 1; t++) {
        int cur = t & 1, nxt = cur ^ 1;
        float4 av2 = *(const float4*)(Aptr + (t+1)*8);
        float4 wv2 = *(const float4*)(Wptr + (t+1)*8);
        #pragma unroll
        for (int k = 0; k < 8; k++) {
            float4 a0 = *(const float4*)&As[cur][k][ty*8];
            float4 a1 = *(const float4*)&As[cur][k][ty*8+4];
            float4 b0 = *(const float4*)&Bs[cur][k][tx*8];
            float4 b1 = *(const float4*)&Bs[cur][k][tx*8+4];
            float ar[8] = {a0.x,a0.y,a0.z,a0.w,a1.x,a1.y,a1.z,a1.w};
            float br[8] = {b0.x,b0.y,b0.z,b0.w,b1.x,b1.y,b1.z,b1.w};
            #pragma unroll
            for (int i = 0; i < 8; i++)
                #pragma unroll
                for (int j = 0; j < 8; j++)
                    acc[i][j] += ar[i] * br[j];
        }
        __syncthreads();
        As[nxt][lc+0][lr] = av2.x; As[nxt][lc+1][lr] = av2.y;
        As[nxt][lc+2][lr] = av2.z; As[nxt][lc+3][lr] = av2.w;
        Bs[nxt][lc+0][lr] = wv2.x; Bs[nxt][lc+1][lr] = wv2.y;
        Bs[nxt][lc+2][lr] = wv2.z; Bs[nxt][lc+3][lr] = wv2.w;
        __syncthreads();
    }
    // epilogue tile NT-1
    {
        int cur = (NT - 1) & 1;
        #pragma unroll
        for (int k = 0; k < 8; k++) {
            float4 a0 = *(const float4*)&As[cur][k][ty*8];
            float4 a1 = *(const float4*)&As[cur][k][ty*8+4];
            float4 b0 = *(const float4*)&Bs[cur][k][tx*8];
            float4 b1 = *(const float4*)&Bs[cur][k][tx*8+4];
            float ar[8] = {a0.x,a0.y,a0.z,a0.w,a1.x,a1.y,a1.z,a1.w};
            float br[8] = {b0.x,b0.y,b0.z,b0.w,b1.x,b1.y,b1.z,b1.w};
            #pragma unroll
            for (int i = 0; i < 8; i++)
                #pragma unroll
                for (int j = 0; j < 8; j++)
                    acc[i][j] += ar[i] * br[j];
        }
    }

    // bias prefetched once
    float bs[8];
    #pragma unroll
    for (int j = 0; j < 8; j++) bs[j] = bias[bias0 + tx*8 + j];

    #pragma unroll
    for (int i = 0; i < 8; i++) {
        int row = row0 + ty*8 + i;
        float* cp = C + row * EMBD + col0 + tx*8;
        float4 o0, o1;
        o0.x = acc[i][0] + bs[0]; o0.y = acc[i][1] + bs[1];
        o0.z = acc[i][2] + bs[2]; o0.w = acc[i][3] + bs[3];
        o1.x = acc[i][4] + bs[4]; o1.y = acc[i][5] + bs[5];
        o1.z = acc[i][6] + bs[6]; o1.w = acc[i][7] + bs[7];
        if (relu) {
            o0.x = fmaxf(o0.x, 0.f); o0.y = fmaxf(o0.y, 0.f);
            o0.z = fmaxf(o0.z, 0.f); o0.w = fmaxf(o0.w, 0.f);
            o1.x = fmaxf(o1.x, 0.f); o1.y = fmaxf(o1.y, 0.f);
            o1.z = fmaxf(o1.z, 0.f); o1.w = fmaxf(o1.w, 0.f);
        }
        *(float4*)cp = o0;
        *(float4*)(cp + 4) = o1;
    }
}

// plain GEMM: C = A @ W^T + bias (opt relu). grid (4, 64)
__global__ __launch_bounds__(256) void sgemm_kernel(
        const float* __restrict__ A, const float* __restrict__ W,
        const float* __restrict__ bias, float* __restrict__ C, int relu) {
    int col0 = blockIdx.x * 128;
    int row0 = blockIdx.y * 128;
    sgemm_core(A, W, bias, C, row0, col0, col0, col0, relu);
}

// fused QKV GEMM: grid (12, 64). sector 0: qp = qsh@Wq^T; 1: kp = x@Wk^T; 2: vp = x@Wv^T
__global__ __launch_bounds__(256) void qkv_kernel(
        const float* __restrict__ qsh, const float* __restrict__ x,
        const float* __restrict__ Wqkv_l, const float* __restrict__ bqkv_l,
        float* __restrict__ qp, float* __restrict__ kp, float* __restrict__ vp) {
    int sector = blockIdx.x >> 2;            // 0,1,2
    int col0 = (blockIdx.x & 3) * 128;       // within 512
    int row0 = blockIdx.y * 128;
    const float* A = (sector == 0) ? qsh : x;
    float* C = (sector == 0) ? qp : (sector == 1) ? kp : vp;
    sgemm_core(A, Wqkv_l, bqkv_l, C, row0, col0, sector*512 + col0, sector*512 + col0, 0);
}

// ---------------- attention: masked causal flash (fp32, exact online softmax) --
__global__ __launch_bounds__(128) void attn_kernel() {
    __shared__ float Ks[64][64];
    __shared__ float Vs[64][64];
    __shared__ float msh[SEQL];
    int tid = threadIdx.x;
    int bh = blockIdx.x;        // 0..63
    int b = bh >> 3, h = bh & 7;
    int qi0 = blockIdx.y * 128;
    for (int u = tid; u < SEQL; u += 128) msh[u] = g_m[u];

    int i = qi0 + tid;          // query row for this thread
    const float scale = 0.125f; // 1/sqrt(64)
    const float* qrow = g_qp + (b*SEQL + i) * EMBD + h*64;
    float qreg[64];
    #pragma unroll
    for (int d = 0; d < 64; d += 4) {
        float4 v = *(const float4*)(qrow + d);
        qreg[d]   = v.x * scale; qreg[d+1] = v.y * scale;
        qreg[d+2] = v.z * scale; qreg[d+3] = v.w * scale;
    }
    float mx = -1e30f, ssum = 0.f;
    float acc[64];
    #pragma unroll
    for (int d = 0; d < 64; d++) acc[d] = 0.f;

    int ntiles = qi0/64 + 2;    // keys needed: [0, qi0+127]
    for (int t = 0; t < ntiles; t++) {
        int j0 = t * 64;
        __syncthreads();
        #pragma unroll
        for (int u = 0; u < 8; u++) {
            int fi = u * 128 + tid;           // float4 index 0..1023
            int row = fi >> 4, c4 = (fi & 15) * 4;
            int base = (b*SEQL + j0 + row) * EMBD + h*64 + c4;
            *(float4*)&Ks[row][c4] = *(const float4*)(g_kp + base);
            *(float4*)&Vs[row][c4] = *(const float4*)(g_vp + base);
        }
        __syncthreads();
        int jlim = i - j0; if (jlim > 63) jlim = 63;
        for (int j = 0; j <= jlim; j++) {
            if (msh[i - (j0 + j)] == 0.f) continue;
            float s = 0.f;
            #pragma unroll
            for (int d = 0; d < 64; d += 4) {
                float4 kv = *(const float4*)&Ks[j][d];
                s += qreg[d]*kv.x + qreg[d+1]*kv.y + qreg[d+2]*kv.z + qreg[d+3]*kv.w;
            }
            if (s > mx) {
                float f = __expf(mx - s);
                ssum *= f;
                #pragma unroll
                for (int d = 0; d < 64; d++) acc[d] *= f;
                mx = s;
            }
            float p = __expf(s - mx);
            ssum += p;
            #pragma unroll
            for (int d = 0; d < 64; d += 4) {
                float4 vv = *(const float4*)&Vs[j][d];
                acc[d]   += p*vv.x; acc[d+1] += p*vv.y;
                acc[d+2] += p*vv.z; acc[d+3] += p*vv.w;
            }
        }
    }
    float inv = 1.0f / ssum;    // diagonal always allowed (m[0]=1 via gumbel[0,0]=10)
    float* orow = g_t0 + (b*SEQL + i) * EMBD + h*64;
    #pragma unroll
    for (int d = 0; d < 64; d += 4) {
        float4 o;
        o.x = acc[d]*inv; o.y = acc[d+1]*inv; o.z = acc[d+2]*inv; o.w = acc[d+3]*inv;
        *(float4*)(orow + d) = o;
    }
}

// ---------------- residual + layernorm ----------------
__global__ __launch_bounds__(128) void addln_kernel(
        const float* __restrict__ a, const float* __restrict__ bsrc,
        const float* __restrict__ s, const float* __restrict__ bb,
        float* __restrict__ y) {
    int row = blockIdx.x, t = threadIdx.x;
    float4 v = ((const float4*)(a + row*EMBD))[t];
    float4 w = ((const float4*)(bsrc + row*EMBD))[t];
    v.x += w.x; v.y += w.y; v.z += w.z; v.w += w.w;
    float sum = v.x + v.y + v.z + v.w;
    float sq  = v.x*v.x + v.y*v.y + v.z*v.z + v.w*v.w;
    __shared__ float r1[4], r2[4];
    #pragma unroll
    for (int o = 16; o; o >>= 1) {
        sum += __shfl_down_sync(0xffffffffu, sum, o);
        sq  += __shfl_down_sync(0xffffffffu, sq,  o);
    }
    if ((t & 31) == 0) { r1[t>>5] = sum; r2[t>>5] = sq; }
    __syncthreads();
    float S  = r1[0] + r1[1] + r1[2] + r1[3];
    float SQ = r2[0] + r2[1] + r2[2] + r2[3];
    float mean = S * (1.0f/EMBD);
    float var  = SQ * (1.0f/EMBD) - mean*mean;
    float inv  = rsqrtf(var + 1e-5f);
    float4 sv = ((const float4*)s)[t], bv = ((const float4*)bb)[t];
    float4 o;
    o.x = (v.x - mean)*inv*sv.x + bv.x;
    o.y = (v.y - mean)*inv*sv.y + bv.y;
    o.z = (v.z - mean)*inv*sv.z + bv.z;
    o.w = (v.w - mean)*inv*sv.w + bv.w;
    ((float4*)(y + row*EMBD))[t] = o;
}

// ---------------- final sigmoid dot ----------------
__global__ __launch_bounds__(256) void pred_kernel(
        const float* __restrict__ w, const float* __restrict__ pb,
        float* __restrict__ out) {
    int warp = threadIdx.x >> 5, lane = threadIdx.x & 31;
    int row = blockIdx.x * 8 + warp;
    const float4* x4 = (const float4*)(g_x + row * EMBD);
    const float4* w4 = (const float4*)w;
    float d = 0.f;
    #pragma unroll
    for (int u = 0; u < 4; u++) {
        float4 xv = x4[lane + 32*u];
        float4 wv = w4[lane + 32*u];
        d += xv.x*wv.x + xv.y*wv.y + xv.z*wv.z + xv.w*wv.w;
    }
    #pragma unroll
    for (int o = 16; o; o >>= 1) d += __shfl_down_sync(0xffffffffu, d, o);
    if (lane == 0) out[row] = 1.0f / (1.0f + expf(-(d + pb[0])));
}

// ---------------- launch ----------------
extern "C" void kernel_launch(void* const* d_in, const int* in_sizes, int n_in,
                              void* d_out, int out_size) {
    const int*   q      = (const int*)  d_in[0];
    const int*   r      = (const int*)  d_in[1];
    const int*   qry    = (const int*)  d_in[2];
    const float* alphas = (const float*)d_in[3];
    const float* gumbel = (const float*)d_in[4];
    const float* inter  = (const float*)d_in[5];
    const float* ex     = (const float*)d_in[6];
    const float* pos    = (const float*)d_in[7];
    const float* Wqkv   = (const float*)d_in[8];
    const float* bqkv   = (const float*)d_in[9];
    const float* Wo     = (const float*)d_in[10];
    const float* bo     = (const float*)d_in[11];
    const float* ln1s   = (const float*)d_in[12];
    const float* ln1b   = (const float*)d_in[13];
    const float* W1     = (const float*)d_in[14];
    const float* b1     = (const float*)d_in[15];
    const float* W2     = (const float*)d_in[16];
    const float* b2     = (const float*)d_in[17];
    const float* ln2s   = (const float*)d_in[18];
    const float* ln2b   = (const float*)d_in[19];
    const float* predw  = (const float*)d_in[20];
    const float* predb  = (const float*)d_in[21];
    float* out = (float*)d_out;

    float *x, *qsh, *qp, *kp, *vp, *t0, *t1, *h, *t2;
    cudaGetSymbolAddress((void**)&x,   g_x);
    cudaGetSymbolAddress((void**)&qsh, g_qsh);
    cudaGetSymbolAddress((void**)&qp,  g_qp);
    cudaGetSymbolAddress((void**)&kp,  g_kp);
    cudaGetSymbolAddress((void**)&vp,  g_vp);
    cudaGetSymbolAddress((void**)&t0,  g_t0);
    cudaGetSymbolAddress((void**)&t1,  g_t1);
    cudaGetSymbolAddress((void**)&h,   g_h);
    cudaGetSymbolAddress((void**)&t2,  g_t2);

    prep_kernel<<<1, 1024>>>(alphas, gumbel, out, out_size > NTOK ? 1 : 0);
    gather_kernel<<<NTOK, 128>>>(q, r, qry, inter, ex, pos);

    dim3 gg(4, 64);    // M/128 x NTOK/128
    dim3 gq(12, 64);   // fused QKV
    for (int l = 0; l < 2; l++) {
        const float* Wqkv_l = Wqkv + (long)l * 1536 * 512;
        const float* bqkv_l = bqkv + l * 1536;
        qkv_kernel<<<gq, 256>>>(qsh, x, Wqkv_l, bqkv_l, qp, kp, vp);
        attn_kernel<<<dim3(64, 8), 128>>>();
        sgemm_kernel<<<gg, 256>>>(t0, Wo + (long)l*512*512, bo + l*512, t1, 0);
        addln_kernel<<<NTOK, 128>>>(qsh, t1, ln1s + l*512, ln1b + l*512, h);
        sgemm_kernel<<<gg, 256>>>(h,  W1 + (long)l*512*512, b1 + l*512, t2, 1);
        sgemm_kernel<<<gg, 256>>>(t2, W2 + (long)l*512*512, b2 + l*512, t1, 0);
        addln_kernel<<<NTOK, 128>>>(h, t1, ln2s + l*512, ln2b + l*512, x);
    }
    pred_kernel<<<1024, 256>>>(predw, predb, out);
}

// round 11
// speedup vs baseline: 1.1317x; 1.1317x over previous
#include <cuda_runtime.h>
#include <math.h>
#include <stdint.h>

#define NTOK 8192
#define SEQL 1024
#define EMBD 512
#define NUMC 10000

// ---------------- scratch (device globals; no allocation allowed) ----------------
__device__ float g_x  [NTOK*EMBD];
__device__ float g_qsh[NTOK*EMBD];
__device__ float g_qp [NTOK*EMBD];
__device__ float g_kp [NTOK*EMBD];
__device__ float g_vp [NTOK*EMBD];
__device__ float g_t0 [NTOK*EMBD];
__device__ float g_t1 [NTOK*EMBD];
__device__ float g_h  [NTOK*EMBD];
__device__ float g_t2 [NTOK*EMBD];
__device__ float g_m  [SEQL];

// ---------------- prep: mask m[t] + L1(alphas) ----------------
__global__ void prep_kernel(const float* __restrict__ alphas,
                            const float* __restrict__ gumbel,
                            float* __restrict__ out, int write_l1) {
    int t = threadIdx.x; // 1024 threads
    float a0 = alphas[2*t], a1 = alphas[2*t+1];
    float l0 = a0 + gumbel[2*t], l1 = a1 + gumbel[2*t+1];
    // argmax(softmax) == argmax(logits); jnp.argmax picks first on tie -> >=
    g_m[t] = (l0 >= l1) ? 1.0f : 0.0f;

    float v = fabsf(a0) + fabsf(a1);
    __shared__ float red[32];
    #pragma unroll
    for (int o = 16; o; o >>= 1) v += __shfl_down_sync(0xffffffffu, v, o);
    if ((t & 31) == 0) red[t >> 5] = v;
    __syncthreads();
    if (t < 32) {
        float w = red[t];
        #pragma unroll
        for (int o = 16; o; o >>= 1) w += __shfl_down_sync(0xffffffffu, w, o);
        if (t == 0 && write_l1) out[NTOK] = w;
    }
}

// ---------------- gather: x = inter[q+C*r]+pos ; qsh = ex[qry] ----------------
__global__ __launch_bounds__(128) void gather_kernel(
        const int* __restrict__ q, const int* __restrict__ r,
        const int* __restrict__ qry,
        const float* __restrict__ inter, const float* __restrict__ ex,
        const float* __restrict__ pos) {
    int n = blockIdx.x, t = threadIdx.x;            // t in [0,128): float4 lanes
    int li = n & (SEQL - 1);
    long ii = (long)(q[n] + NUMC * r[n]) * 128;
    long ei = (long)qry[n] * 128;
    float4 iv = ((const float4*)inter)[ii + t];
    float4 pv = ((const float4*)pos)[li * 128 + t];
    float4 xv;
    xv.x = iv.x + pv.x; xv.y = iv.y + pv.y; xv.z = iv.z + pv.z; xv.w = iv.w + pv.w;
    ((float4*)g_x)[n * 128 + t] = xv;
    ((float4*)g_qsh)[n * 128 + t] = ((const float4*)ex)[ei + t];
}

// ---------------- tf32 helpers ----------------
__device__ __forceinline__ float f2tf(float x) {
    uint32_t u;
    asm("cvt.rna.tf32.f32 %0, %1;" : "=r"(u) : "f"(x));
    return __uint_as_float(u);
}
__device__ __forceinline__ void mma_tf32(float c[4], const uint32_t a[4], const uint32_t b[2]) {
    asm volatile(
        "mma.sync.aligned.m16n8k8.row.col.f32.tf32.tf32.f32 "
        "{%0,%1,%2,%3}, {%4,%5,%6,%7}, {%8,%9}, {%0,%1,%2,%3};"
        : "+f"(c[0]), "+f"(c[1]), "+f"(c[2]), "+f"(c[3])
        : "r"(a[0]), "r"(a[1]), "r"(a[2]), "r"(a[3]), "r"(b[0]), "r"(b[1]));
}

// ---------------- SGEMM core: 128x128 tile, BK=8, double-buffered, tf32 MMA ----
// C[row0.., col0..] = A[N,512] @ W[wrow0..,512]^T + bias (opt relu)
// 256 threads = 8 warps as 2(m) x 4(n); warp tile 64x32; atoms m16n8k8.
__device__ __forceinline__ void sgemm_core(
        const float* __restrict__ A, const float* __restrict__ W,
        const float* __restrict__ bias, float* __restrict__ C,
        int row0, int col0, int wrow0, int bias0, int relu) {
    __shared__ float As[2][8][136];   // [k][m], padded: frag reads bank-free
    __shared__ float Bs[2][8][136];   // [k][n]
    int tid = threadIdx.x;
    int lr = tid >> 1;             // 0..127
    int lc = (tid & 1) * 4;        // 0 or 4
    const float* Aptr = A + (row0 + lr) * EMBD + lc;
    const float* Wptr = W + (wrow0 + lr) * EMBD + lc;

    int warp = tid >> 5, lane = tid & 31;
    int g = lane >> 2, ctg = lane & 3;     // group row / thread-in-group
    int warpM = (warp >> 2) * 64;          // 0 or 64
    int warpN = (warp & 3) * 32;           // 0,32,64,96

    float acc[4][4][4];                    // [ma][na][c0..c3]
    #pragma unroll
    for (int i = 0; i < 4; i++)
        #pragma unroll
        for (int j = 0; j < 4; j++)
            #pragma unroll
            for (int c = 0; c < 4; c++) acc[i][j][c] = 0.f;

    // prologue: stage tile 0 (converted to tf32)
    {
        float4 av = *(const float4*)(Aptr);
        float4 wv = *(const float4*)(Wptr);
        As[0][lc+0][lr] = f2tf(av.x); As[0][lc+1][lr] = f2tf(av.y);
        As[0][lc+2][lr] = f2tf(av.z); As[0][lc+3][lr] = f2tf(av.w);
        Bs[0][lc+0][lr] = f2tf(wv.x); Bs[0][lc+1][lr] = f2tf(wv.y);
        Bs[0][lc+2][lr] = f2tf(wv.z); Bs[0][lc+3][lr] = f2tf(wv.w);
    }
    __syncthreads();

    const int NT = EMBD / 8;       // 64 k-tiles
    for (int t = 0; t < NT - 1; t++) {
        int cur = t & 1, nxt = cur ^ 1;
        float4 av2 = *(const float4*)(Aptr + (t+1)*8);
        float4 wv2 = *(const float4*)(Wptr + (t+1)*8);

        // fragments from current buffer
        uint32_t af[4][4], bf[4][2];
        #pragma unroll
        for (int ma = 0; ma < 4; ma++) {
            int m = warpM + ma*16 + g;
            af[ma][0] = __float_as_uint(As[cur][ctg  ][m]);
            af[ma][1] = __float_as_uint(As[cur][ctg  ][m+8]);
            af[ma][2] = __float_as_uint(As[cur][ctg+4][m]);
            af[ma][3] = __float_as_uint(As[cur][ctg+4][m+8]);
        }
        #pragma unroll
        for (int na = 0; na < 4; na++) {
            int n = warpN + na*8 + g;
            bf[na][0] = __float_as_uint(Bs[cur][ctg  ][n]);
            bf[na][1] = __float_as_uint(Bs[cur][ctg+4][n]);
        }
        #pragma unroll
        for (int ma = 0; ma < 4; ma++)
            #pragma unroll
            for (int na = 0; na < 4; na++)
                mma_tf32(acc[ma][na], af[ma], bf[na]);

        __syncthreads();
        As[nxt][lc+0][lr] = f2tf(av2.x); As[nxt][lc+1][lr] = f2tf(av2.y);
        As[nxt][lc+2][lr] = f2tf(av2.z); As[nxt][lc+3][lr] = f2tf(av2.w);
        Bs[nxt][lc+0][lr] = f2tf(wv2.x); Bs[nxt][lc+1][lr] = f2tf(wv2.y);
        Bs[nxt][lc+2][lr] = f2tf(wv2.z); Bs[nxt][lc+3][lr] = f2tf(wv2.w);
        __syncthreads();
    }
    // epilogue tile NT-1
    {
        int cur = (NT - 1) & 1;
        uint32_t af[4][4], bf[4][2];
        #pragma unroll
        for (int ma = 0; ma < 4; ma++) {
            int m = warpM + ma*16 + g;
            af[ma][0] = __float_as_uint(As[cur][ctg  ][m]);
            af[ma][1] = __float_as_uint(As[cur][ctg  ][m+8]);
            af[ma][2] = __float_as_uint(As[cur][ctg+4][m]);
            af[ma][3] = __float_as_uint(As[cur][ctg+4][m+8]);
        }
        #pragma unroll
        for (int na = 0; na < 4; na++) {
            int n = warpN + na*8 + g;
            bf[na][0] = __float_as_uint(Bs[cur][ctg  ][n]);
            bf[na][1] = __float_as_uint(Bs[cur][ctg+4][n]);
        }
        #pragma unroll
        for (int ma = 0; ma < 4; ma++)
            #pragma unroll
            for (int na = 0; na < 4; na++)
                mma_tf32(acc[ma][na], af[ma], bf[na]);
    }

    // bias prefetch: 2 cols per n-atom
    float bsv[4][2];
    #pragma unroll
    for (int na = 0; na < 4; na++) {
        int c = bias0 + warpN + na*8 + ctg*2;
        bsv[na][0] = bias[c]; bsv[na][1] = bias[c+1];
    }

    #pragma unroll
    for (int ma = 0; ma < 4; ma++) {
        int row = row0 + warpM + ma*16 + g;
        #pragma unroll
        for (int na = 0; na < 4; na++) {
            int col = col0 + warpN + na*8 + ctg*2;
            float2 v0, v1;
            v0.x = acc[ma][na][0] + bsv[na][0];
            v0.y = acc[ma][na][1] + bsv[na][1];
            v1.x = acc[ma][na][2] + bsv[na][0];
            v1.y = acc[ma][na][3] + bsv[na][1];
            if (relu) {
                v0.x = fmaxf(v0.x, 0.f); v0.y = fmaxf(v0.y, 0.f);
                v1.x = fmaxf(v1.x, 0.f); v1.y = fmaxf(v1.y, 0.f);
            }
            *(float2*)&C[row * EMBD + col]       = v0;
            *(float2*)&C[(row + 8) * EMBD + col] = v1;
        }
    }
}

// plain GEMM: C = A @ W^T + bias (opt relu). grid (4, 64)
__global__ __launch_bounds__(256) void sgemm_kernel(
        const float* __restrict__ A, const float* __restrict__ W,
        const float* __restrict__ bias, float* __restrict__ C, int relu) {
    int col0 = blockIdx.x * 128;
    int row0 = blockIdx.y * 128;
    sgemm_core(A, W, bias, C, row0, col0, col0, col0, relu);
}

// fused QKV GEMM: grid (12, 64). sector 0: qp = qsh@Wq^T; 1: kp = x@Wk^T; 2: vp = x@Wv^T
__global__ __launch_bounds__(256) void qkv_kernel(
        const float* __restrict__ qsh, const float* __restrict__ x,
        const float* __restrict__ Wqkv_l, const float* __restrict__ bqkv_l,
        float* __restrict__ qp, float* __restrict__ kp, float* __restrict__ vp) {
    int sector = blockIdx.x >> 2;            // 0,1,2
    int col0 = (blockIdx.x & 3) * 128;       // within 512
    int row0 = blockIdx.y * 128;
    const float* A = (sector == 0) ? qsh : x;
    float* C = (sector == 0) ? qp : (sector == 1) ? kp : vp;
    sgemm_core(A, Wqkv_l, bqkv_l, C, row0, col0, sector*512 + col0, sector*512 + col0, 0);
}

// ---------------- attention: masked causal flash, thread-pair per query row ----
// 256 threads: thread (2r+half) handles query row qi0+r, head-dim half `half`.
// Inner j-loop is warp-uniform; causal+mask folded into s=-3e38 (p underflows
// to 0) so the pair-combining shfl_xor is always warp-legal.
__global__ __launch_bounds__(256) void attn_kernel() {
    __shared__ float Ks[64][64];
    __shared__ float Vs[64][64];
    __shared__ float msh[SEQL];
    int tid = threadIdx.x;
    int bh = blockIdx.x;        // 0..63
    int b = bh >> 3, h = bh & 7;
    int qi0 = blockIdx.y * 128;
    for (int u = tid; u < SEQL; u += 256) msh[u] = g_m[u];

    int r = tid >> 1, half = tid & 1;
    int i = qi0 + r;                    // query row
    int imax_w = qi0 + ((tid | 31) >> 1);  // max query row in this warp (uniform)
    const float scale = 0.125f;         // 1/sqrt(64)
    const float* qrow = g_qp + (b*SEQL + i) * EMBD + h*64 + half*32;
    float qreg[32];
    #pragma unroll
    for (int d = 0; d < 32; d += 4) {
        float4 v = *(const float4*)(qrow + d);
        qreg[d]   = v.x * scale; qreg[d+1] = v.y * scale;
        qreg[d+2] = v.z * scale; qreg[d+3] = v.w * scale;
    }
    float mx = -1e30f, ssum = 0.f;
    float acc[32];
    #pragma unroll
    for (int d = 0; d < 32; d++) acc[d] = 0.f;

    int ntiles = qi0/64 + 2;    // keys needed: [0, qi0+127]
    for (int t = 0; t < ntiles; t++) {
        int j0 = t * 64;
        __syncthreads();
        #pragma unroll
        for (int u = 0; u < 4; u++) {
            int fi = u * 256 + tid;           // float4 index 0..1023
            int row = fi >> 4, c4 = (fi & 15) * 4;
            int base = (b*SEQL + j0 + row) * EMBD + h*64 + c4;
            *(float4*)&Ks[row][c4] = *(const float4*)(g_kp + base);
            *(float4*)&Vs[row][c4] = *(const float4*)(g_vp + base);
        }
        __syncthreads();
        int jlim = i - j0;                    // per-row causal limit
        int jlim_w = imax_w - j0;             // warp-uniform loop bound
        if (jlim_w > 63) jlim_w = 63;
        for (int j = 0; j <= jlim_w; j++) {
            // partial dot over this thread's 32 dims
            float sp = 0.f;
            #pragma unroll
            for (int d = 0; d < 32; d += 4) {
                float4 kv = *(const float4*)&Ks[j][half*32 + d];
                sp += qreg[d]*kv.x + qreg[d+1]*kv.y + qreg[d+2]*kv.z + qreg[d+3]*kv.w;
            }
            float s = sp + __shfl_xor_sync(0xffffffffu, sp, 1);
            int mi = i - j0 - j;              // distance; valid iff >= 0
            bool ok = (j <= jlim) && (msh[mi & (SEQL-1)] != 0.f);
            if (!ok) s = -3e38f;              // p underflows to exactly 0
            if (s > mx) {
                float f = __expf(mx - s);
                ssum *= f;
                #pragma unroll
                for (int d = 0; d < 32; d++) acc[d] *= f;
                mx = s;
            }
            float p = __expf(s - mx);
            ssum += p;
            if (ok) {
                #pragma unroll
                for (int d = 0; d < 32; d += 4) {
                    float4 vv = *(const float4*)&Vs[j][half*32 + d];
                    acc[d]   += p*vv.x; acc[d+1] += p*vv.y;
                    acc[d+2] += p*vv.z; acc[d+3] += p*vv.w;
                }
            }
        }
    }
    float inv = 1.0f / ssum;    // diagonal always allowed (m[0]=1 via gumbel[0,0]=10)
    float* orow = g_t0 + (b*SEQL + i) * EMBD + h*64 + half*32;
    #pragma unroll
    for (int d = 0; d < 32; d += 4) {
        float4 o;
        o.x = acc[d]*inv; o.y = acc[d+1]*inv; o.z = acc[d+2]*inv; o.w = acc[d+3]*inv;
        *(float4*)(orow + d) = o;
    }
}

// ---------------- residual + layernorm ----------------
__global__ __launch_bounds__(128) void addln_kernel(
        const float* __restrict__ a, const float* __restrict__ bsrc,
        const float* __restrict__ s, const float* __restrict__ bb,
        float* __restrict__ y) {
    int row = blockIdx.x, t = threadIdx.x;
    float4 v = ((const float4*)(a + row*EMBD))[t];
    float4 w = ((const float4*)(bsrc + row*EMBD))[t];
    v.x += w.x; v.y += w.y; v.z += w.z; v.w += w.w;
    float sum = v.x + v.y + v.z + v.w;
    float sq  = v.x*v.x + v.y*v.y + v.z*v.z + v.w*v.w;
    __shared__ float r1[4], r2[4];
    #pragma unroll
    for (int o = 16; o; o >>= 1) {
        sum += __shfl_down_sync(0xffffffffu, sum, o);
        sq  += __shfl_down_sync(0xffffffffu, sq,  o);
    }
    if ((t & 31) == 0) { r1[t>>5] = sum; r2[t>>5] = sq; }
    __syncthreads();
    float S  = r1[0] + r1[1] + r1[2] + r1[3];
    float SQ = r2[0] + r2[1] + r2[2] + r2[3];
    float mean = S * (1.0f/EMBD);
    float var  = SQ * (1.0f/EMBD) - mean*mean;
    float inv  = rsqrtf(var + 1e-5f);
    float4 sv = ((const float4*)s)[t], bv = ((const float4*)bb)[t];
    float4 o;
    o.x = (v.x - mean)*inv*sv.x + bv.x;
    o.y = (v.y - mean)*inv*sv.y + bv.y;
    o.z = (v.z - mean)*inv*sv.z + bv.z;
    o.w = (v.w - mean)*inv*sv.w + bv.w;
    ((float4*)(y + row*EMBD))[t] = o;
}

// ---------------- final sigmoid dot ----------------
__global__ __launch_bounds__(256) void pred_kernel(
        const float* __restrict__ w, const float* __restrict__ pb,
        float* __restrict__ out) {
    int warp = threadIdx.x >> 5, lane = threadIdx.x & 31;
    int row = blockIdx.x * 8 + warp;
    const float4* x4 = (const float4*)(g_x + row * EMBD);
    const float4* w4 = (const float4*)w;
    float d = 0.f;
    #pragma unroll
    for (int u = 0; u < 4; u++) {
        float4 xv = x4[lane + 32*u];
        float4 wv = w4[lane + 32*u];
        d += xv.x*wv.x + xv.y*wv.y + xv.z*wv.z + xv.w*wv.w;
    }
    #pragma unroll
    for (int o = 16; o; o >>= 1) d += __shfl_down_sync(0xffffffffu, d, o);
    if (lane == 0) out[row] = 1.0f / (1.0f + expf(-(d + pb[0])));
}

// ---------------- launch ----------------
extern "C" void kernel_launch(void* const* d_in, const int* in_sizes, int n_in,
                              void* d_out, int out_size) {
    const int*   q      = (const int*)  d_in[0];
    const int*   r      = (const int*)  d_in[1];
    const int*   qry    = (const int*)  d_in[2];
    const float* alphas = (const float*)d_in[3];
    const float* gumbel = (const float*)d_in[4];
    const float* inter  = (const float*)d_in[5];
    const float* ex     = (const float*)d_in[6];
    const float* pos    = (const float*)d_in[7];
    const float* Wqkv   = (const float*)d_in[8];
    const float* bqkv   = (const float*)d_in[9];
    const float* Wo     = (const float*)d_in[10];
    const float* bo     = (const float*)d_in[11];
    const float* ln1s   = (const float*)d_in[12];
    const float* ln1b   = (const float*)d_in[13];
    const float* W1     = (const float*)d_in[14];
    const float* b1     = (const float*)d_in[15];
    const float* W2     = (const float*)d_in[16];
    const float* b2     = (const float*)d_in[17];
    const float* ln2s   = (const float*)d_in[18];
    const float* ln2b   = (const float*)d_in[19];
    const float* predw  = (const float*)d_in[20];
    const float* predb  = (const float*)d_in[21];
    float* out = (float*)d_out;

    float *x, *qsh, *qp, *kp, *vp, *t0, *t1, *h, *t2;
    cudaGetSymbolAddress((void**)&x,   g_x);
    cudaGetSymbolAddress((void**)&qsh, g_qsh);
    cudaGetSymbolAddress((void**)&qp,  g_qp);
    cudaGetSymbolAddress((void**)&kp,  g_kp);
    cudaGetSymbolAddress((void**)&vp,  g_vp);
    cudaGetSymbolAddress((void**)&t0,  g_t0);
    cudaGetSymbolAddress((void**)&t1,  g_t1);
    cudaGetSymbolAddress((void**)&h,   g_h);
    cudaGetSymbolAddress((void**)&t2,  g_t2);

    prep_kernel<<<1, 1024>>>(alphas, gumbel, out, out_size > NTOK ? 1 : 0);
    gather_kernel<<<NTOK, 128>>>(q, r, qry, inter, ex, pos);

    dim3 gg(4, 64);    // M/128 x NTOK/128
    dim3 gq(12, 64);   // fused QKV
    for (int l = 0; l < 2; l++) {
        const float* Wqkv_l = Wqkv + (long)l * 1536 * 512;
        const float* bqkv_l = bqkv + l * 1536;
        qkv_kernel<<<gq, 256>>>(qsh, x, Wqkv_l, bqkv_l, qp, kp, vp);
        attn_kernel<<<dim3(64, 8), 256>>>();
        sgemm_kernel<<<gg, 256>>>(t0, Wo + (long)l*512*512, bo + l*512, t1, 0);
        addln_kernel<<<NTOK, 128>>>(qsh, t1, ln1s + l*512, ln1b + l*512, h);
        sgemm_kernel<<<gg, 256>>>(h,  W1 + (long)l*512*512, b1 + l*512, t2, 1);
        sgemm_kernel<<<gg, 256>>>(t2, W2 + (long)l*512*512, b2 + l*512, t1, 0);
        addln_kernel<<<NTOK, 128>>>(h, t1, ln2s + l*512, ln2b + l*512, x);
    }
    pred_kernel<<<1024, 256>>>(predw, predb, out);
}